// round 14
// baseline (speedup 1.0000x reference)
#include <cuda_runtime.h>

// out[i] = cos(x[i]) * cos(theta[i & 63])
// N = 33,554,432 fp32 -> 8,388,608 float4.
//
// FINAL kernel — converged at the DRAM roofline after 12 measured rounds.
// Six consecutive confirmations: 45.12-45.28 us wall, 36.1-37.5 us kernel,
// 5.68-5.89 TB/s (71-74.5% of 8 TB/s spec = HBM3e mixed 1:1 read:write
// ceiling). SM ~85% idle (issue ~15%, fma ~6%).
// Wins: MLP 1->4 (-8us), cosf->__cosf + shared theta table (-7us).
// Neutral: MLP 8, block 256/512, persistent grid, 256-bit access, L2
// eviction hints, store phasing/batching, CTA-level direction phasing.
// Closed: L2 persistence (carveout=0; device-limit changes forbidden),
// output narrowing (fp32 contract), input reuse (random data), TMA (same
// path-independent LTS cap). 268 MB traffic is compulsory.
//
// Config: 512-thread CTAs, 64B per thread, front-batched MLP=4 LDG.128,
// __cosf (MUFU) with accurate-cosf shared theta table (64 entries).
// Per-thread inner stride = 512 float4 = 2048 floats == 0 mod 64, so each
// thread's theta vector is invariant across its 4 iterations.

#define THREADS 512
#define UNROLL  4
#define CHUNK   (THREADS * UNROLL)     // 2048 float4 per block

__global__ void __launch_bounds__(THREADS) qab_kernel(
    const float4* __restrict__ x4,
    const float* __restrict__ theta,
    float4* __restrict__ out4,
    int nvec)
{
    __shared__ float ct[64];
    if (threadIdx.x < 64) {
        ct[threadIdx.x] = cosf(theta[threadIdx.x]);   // accurate; 64 values
    }
    __syncthreads();

    const int base = blockIdx.x * CHUNK + threadIdx.x;
    const int t = (base << 2) & 63;                    // 16B-aligned theta slot
    const float4 c = *reinterpret_cast<const float4*>(&ct[t]);

    if (base + (UNROLL - 1) * THREADS < nvec) {
        // Front-batch all 4 LDG.128 (MLP=4)
        float4 v[UNROLL];
        #pragma unroll
        for (int k = 0; k < UNROLL; k++)
            v[k] = x4[base + k * THREADS];

        #pragma unroll
        for (int k = 0; k < UNROLL; k++) {
            float4 r;
            r.x = __cosf(v[k].x) * c.x;
            r.y = __cosf(v[k].y) * c.y;
            r.z = __cosf(v[k].z) * c.z;
            r.w = __cosf(v[k].w) * c.w;
            out4[base + k * THREADS] = r;
        }
    } else {
        // Tail path (unused for the shipped shape; kept for generality)
        #pragma unroll
        for (int k = 0; k < UNROLL; k++) {
            int i = base + k * THREADS;
            if (i < nvec) {
                float4 v = x4[i];
                float4 r;
                r.x = __cosf(v.x) * c.x;
                r.y = __cosf(v.y) * c.y;
                r.z = __cosf(v.z) * c.z;
                r.w = __cosf(v.w) * c.w;
                out4[i] = r;
            }
        }
    }
}

extern "C" void kernel_launch(void* const* d_in, const int* in_sizes, int n_in,
                              void* d_out, int out_size)
{
    const float* x     = (const float*)d_in[0];
    const float* theta = (const float*)d_in[1];
    float* out         = (float*)d_out;

    int n    = out_size;          // total elements (33,554,432)
    int nvec = n >> 2;            // float4 count (8,388,608)

    int blocks = (nvec + CHUNK - 1) / CHUNK;   // 4096 for the shipped shape

    qab_kernel<<<blocks, THREADS>>>(
        (const float4*)x, theta, (float4*)out, nvec);
}

// round 15
// speedup vs baseline: 1.0375x; 1.0375x over previous
#include <cuda_runtime.h>

// out[i] = cos(x[i]) * cos(theta[i & 63])
// N = 33,554,432 fp32 -> 8,388,608 float4.
//
// Block-size axis completion: 1024-thread CTAs, UNROLL=2 (same 2048 float4
// per block, same 2048 threads/SM, half the CTA streams per SM). All other
// structure identical to the seven-times-confirmed best config (45.12-45.28us
// wall at the HBM3e mixed 1:1 r:w ceiling, ~5.86 TB/s, SM ~85% idle).
// Per-thread inner stride = 1024 float4 = 4096 floats == 0 mod 64, so each
// thread's theta vector is invariant across its 2 iterations.

#define THREADS 1024
#define UNROLL  2
#define CHUNK   (THREADS * UNROLL)     // 2048 float4 per block

__global__ void __launch_bounds__(THREADS) qab_kernel(
    const float4* __restrict__ x4,
    const float* __restrict__ theta,
    float4* __restrict__ out4,
    int nvec)
{
    __shared__ float ct[64];
    if (threadIdx.x < 64) {
        ct[threadIdx.x] = cosf(theta[threadIdx.x]);   // accurate; 64 values
    }
    __syncthreads();

    const int base = blockIdx.x * CHUNK + threadIdx.x;
    const int t = (base << 2) & 63;                    // 16B-aligned theta slot
    const float4 c = *reinterpret_cast<const float4*>(&ct[t]);

    if (base + (UNROLL - 1) * THREADS < nvec) {
        // Front-batch both LDG.128 (MLP=2 per thread, 2048 threads/SM)
        float4 v[UNROLL];
        #pragma unroll
        for (int k = 0; k < UNROLL; k++)
            v[k] = x4[base + k * THREADS];

        #pragma unroll
        for (int k = 0; k < UNROLL; k++) {
            float4 r;
            r.x = __cosf(v[k].x) * c.x;
            r.y = __cosf(v[k].y) * c.y;
            r.z = __cosf(v[k].z) * c.z;
            r.w = __cosf(v[k].w) * c.w;
            out4[base + k * THREADS] = r;
        }
    } else {
        // Tail path (unused for the shipped shape; kept for generality)
        #pragma unroll
        for (int k = 0; k < UNROLL; k++) {
            int i = base + k * THREADS;
            if (i < nvec) {
                float4 v = x4[i];
                float4 r;
                r.x = __cosf(v.x) * c.x;
                r.y = __cosf(v.y) * c.y;
                r.z = __cosf(v.z) * c.z;
                r.w = __cosf(v.w) * c.w;
                out4[i] = r;
            }
        }
    }
}

extern "C" void kernel_launch(void* const* d_in, const int* in_sizes, int n_in,
                              void* d_out, int out_size)
{
    const float* x     = (const float*)d_in[0];
    const float* theta = (const float*)d_in[1];
    float* out         = (float*)d_out;

    int n    = out_size;          // total elements (33,554,432)
    int nvec = n >> 2;            // float4 count (8,388,608)

    int blocks = (nvec + CHUNK - 1) / CHUNK;   // 4096 for the shipped shape

    qab_kernel<<<blocks, THREADS>>>(
        (const float4*)x, theta, (float4*)out, nvec);
}